// round 3
// baseline (speedup 1.0000x reference)
#include <cuda_runtime.h>

#define NBLOCKS  1536
#define NTHREADS 256
// total threads = 393216 = 2^17 * 3  -> divisible by 3, and n4 / total = 16 exactly
// for the bench shape (n4 = 6,291,456).

__device__ float        g_pts[NBLOCKS];
__device__ float        g_prs[NBLOCKS];
__device__ unsigned int g_ctr = 0;   // reset by the last block each call

__device__ __forceinline__ float wrap_angle(float a) {
    const float PI  = 3.14159265358979323846f;
    const float TPI = 6.28318530717958647692f;
    a = (a >  PI) ? a - TPI : a;
    a = (a < -PI) ? a + TPI : a;
    return a;
}

// MASK bit j set -> lane j of the float4 is a rotation channel (compile-time).
template <unsigned MASK>
__device__ __forceinline__ void accum_m(float4 p, float4 t,
                                        float& ts, float& rs) {
    const float pe[4] = {p.x, p.y, p.z, p.w};
    const float te[4] = {t.x, t.y, t.z, t.w};
    #pragma unroll
    for (int j = 0; j < 4; j++) {
        if ((MASK >> j) & 1u) {
            float dw = wrap_angle(pe[j]) - wrap_angle(te[j]);
            rs += dw * dw;
        } else {
            float d = pe[j] - te[j];
            ts += d * d;
        }
    }
}

template <unsigned MASK>
__device__ __forceinline__ void mainloop(const float4* __restrict__ p4,
                                         const float4* __restrict__ t4,
                                         unsigned v0, unsigned total,
                                         unsigned n4,
                                         float& ts, float& rs) {
    unsigned v = v0;
    // Unroll x2: batch 4 x 16B streaming loads before compute.
    for (; v + total < n4; v += 2u * total) {
        float4 p0 = __ldcs(p4 + v);
        float4 t0 = __ldcs(t4 + v);
        float4 p1 = __ldcs(p4 + v + total);
        float4 t1 = __ldcs(t4 + v + total);
        accum_m<MASK>(p0, t0, ts, rs);
        accum_m<MASK>(p1, t1, ts, rs);
    }
    if (v < n4) {   // tail (empty for the bench shape)
        accum_m<MASK>(__ldcs(p4 + v), __ldcs(t4 + v), ts, rs);
    }
}

__global__ void __launch_bounds__(NTHREADS)
wmse_kernel(const float4* __restrict__ p4, const float4* __restrict__ t4,
            unsigned n4, float* __restrict__ out) {
    const unsigned total = NBLOCKS * NTHREADS;     // divisible by 3
    const unsigned tid   = blockIdx.x * NTHREADS + threadIdx.x;

    float ts = 0.0f, rs = 0.0f;

    // v % 3 is invariant across the grid-stride loop (total % 3 == 0), so the
    // rotation-lane mask is constant per thread:
    //   m=0 -> channels {0,1,2,3} -> rot lanes 0b1000
    //   m=1 -> channels {4,5,0,1} -> rot lanes 0b0011
    //   m=2 -> channels {2,3,4,5} -> rot lanes 0b1110
    unsigned m = tid % 3u;
    if (m == 0u)      mainloop<0x8u>(p4, t4, tid, total, n4, ts, rs);
    else if (m == 1u) mainloop<0x3u>(p4, t4, tid, total, n4, ts, rs);
    else              mainloop<0xEu>(p4, t4, tid, total, n4, ts, rs);

    // Block reduction
    #pragma unroll
    for (int o = 16; o > 0; o >>= 1) {
        ts += __shfl_xor_sync(0xffffffffu, ts, o);
        rs += __shfl_xor_sync(0xffffffffu, rs, o);
    }
    __shared__ float sts[NTHREADS / 32];
    __shared__ float srs[NTHREADS / 32];
    int lane = threadIdx.x & 31;
    int warp = threadIdx.x >> 5;
    if (lane == 0) { sts[warp] = ts; srs[warp] = rs; }
    __syncthreads();

    __shared__ bool isLast;
    if (threadIdx.x == 0) {
        float bts = 0.0f, brs = 0.0f;
        #pragma unroll
        for (int w = 0; w < NTHREADS / 32; w++) { bts += sts[w]; brs += srs[w]; }
        g_pts[blockIdx.x] = bts;
        g_prs[blockIdx.x] = brs;
        __threadfence();
        unsigned prev = atomicAdd(&g_ctr, 1u);
        isLast = (prev == (unsigned)gridDim.x - 1u);
    }
    __syncthreads();

    if (isLast) {
        __threadfence();
        float a = 0.0f, b = 0.0f;
        for (unsigned i = threadIdx.x; i < NBLOCKS; i += NTHREADS) {
            a += g_pts[i];
            b += g_prs[i];
        }
        #pragma unroll
        for (int o = 16; o > 0; o >>= 1) {
            a += __shfl_xor_sync(0xffffffffu, a, o);
            b += __shfl_xor_sync(0xffffffffu, b, o);
        }
        __syncthreads();                 // sts/srs reuse
        if (lane == 0) { sts[warp] = a; srs[warp] = b; }
        __syncthreads();
        if (threadIdx.x == 0) {
            float A = 0.0f, B = 0.0f;
            #pragma unroll
            for (int w = 0; w < NTHREADS / 32; w++) { A += sts[w]; B += srs[w]; }
            g_ctr = 0;                   // rearm for the next graph replay
            double cnt        = 2.0 * (double)n4;           // elems / 2
            double trans_loss = (double)A / cnt;            // TRANS_WEIGHT=1
            double rot_loss   = ((double)B / cnt) * 100.0;  // ROT_WEIGHT=100
            out[0] = (float)(trans_loss + rot_loss);
            out[1] = (float)trans_loss;
            out[2] = (float)rot_loss;
        }
    }
}

extern "C" void kernel_launch(void* const* d_in, const int* in_sizes, int n_in,
                              void* d_out, int out_size) {
    const float4* pred4   = (const float4*)d_in[0];
    const float4* target4 = (const float4*)d_in[1];
    unsigned n4 = (unsigned)(in_sizes[0] / 4);

    wmse_kernel<<<NBLOCKS, NTHREADS>>>(pred4, target4, n4, (float*)d_out);
}

// round 4
// speedup vs baseline: 2.0526x; 2.0526x over previous
#include <cuda_runtime.h>

#define NBLOCKS  1536
#define NTHREADS 256
// total = 393,216 threads, divisible by 3 -> v % 3 loop-invariant per thread.

__device__ float        g_pts[NBLOCKS];
__device__ float        g_prs[NBLOCKS];
__device__ unsigned int g_ctr = 0;   // reset by the last block each call

__device__ __forceinline__ float wrap_angle(float a) {
    const float PI  = 3.14159265358979323846f;
    const float TPI = 6.28318530717958647692f;
    a = (a >  PI) ? a - TPI : a;
    a = (a < -PI) ? a + TPI : a;
    return a;
}

__global__ void __launch_bounds__(NTHREADS)
wmse_kernel(const float4* __restrict__ p4, const float4* __restrict__ t4,
            unsigned n4, float* __restrict__ out) {
    const unsigned total = NBLOCKS * NTHREADS;     // divisible by 3
    const unsigned tid   = blockIdx.x * NTHREADS + threadIdx.x;

    // Rotation-lane pattern of float4 #v depends only on v % 3, which equals
    // tid % 3 for every iteration (stride divisible by 3):
    //   m=0 -> channels {0,1,2,3} -> rot lanes {3}
    //   m=1 -> channels {4,5,0,1} -> rot lanes {0,1}
    //   m=2 -> channels {2,3,4,5} -> rot lanes {1,2,3}
    const unsigned m = tid % 3u;
    float4 rw;                                      // 1.0 where rotation lane
    rw.x = (m == 1u) ? 1.0f : 0.0f;
    rw.y = (m != 0u) ? 1.0f : 0.0f;
    rw.z = (m == 2u) ? 1.0f : 0.0f;
    rw.w = (m != 1u) ? 1.0f : 0.0f;
    float4 tw;                                      // complement
    tw.x = 1.0f - rw.x;  tw.y = 1.0f - rw.y;
    tw.z = 1.0f - rw.z;  tw.w = 1.0f - rw.w;

    float ts = 0.0f, rs = 0.0f;

    // Simple grid-stride loop, one float4 pair per iteration (R1-proven).
    for (unsigned v = tid; v < n4; v += total) {
        float4 p = p4[v];
        float4 t = t4[v];

        float dx = p.x - t.x, dy = p.y - t.y, dz = p.z - t.z, dwv = p.w - t.w;
        float ex = wrap_angle(p.x) - wrap_angle(t.x);
        float ey = wrap_angle(p.y) - wrap_angle(t.y);
        float ez = wrap_angle(p.z) - wrap_angle(t.z);
        float ew = wrap_angle(p.w) - wrap_angle(t.w);

        ts = fmaf(dx * dx, tw.x, ts);
        ts = fmaf(dy * dy, tw.y, ts);
        ts = fmaf(dz * dz, tw.z, ts);
        ts = fmaf(dwv * dwv, tw.w, ts);
        rs = fmaf(ex * ex, rw.x, rs);
        rs = fmaf(ey * ey, rw.y, rs);
        rs = fmaf(ez * ez, rw.z, rs);
        rs = fmaf(ew * ew, rw.w, rs);
    }

    // Block reduction
    #pragma unroll
    for (int o = 16; o > 0; o >>= 1) {
        ts += __shfl_xor_sync(0xffffffffu, ts, o);
        rs += __shfl_xor_sync(0xffffffffu, rs, o);
    }
    __shared__ float sts[NTHREADS / 32];
    __shared__ float srs[NTHREADS / 32];
    int lane = threadIdx.x & 31;
    int warp = threadIdx.x >> 5;
    if (lane == 0) { sts[warp] = ts; srs[warp] = rs; }
    __syncthreads();

    __shared__ bool isLast;
    if (threadIdx.x == 0) {
        float bts = 0.0f, brs = 0.0f;
        #pragma unroll
        for (int w = 0; w < NTHREADS / 32; w++) { bts += sts[w]; brs += srs[w]; }
        g_pts[blockIdx.x] = bts;
        g_prs[blockIdx.x] = brs;
        __threadfence();
        unsigned prev = atomicAdd(&g_ctr, 1u);
        isLast = (prev == (unsigned)gridDim.x - 1u);
    }
    __syncthreads();

    if (isLast) {
        __threadfence();
        float a = 0.0f, b = 0.0f;
        for (unsigned i = threadIdx.x; i < NBLOCKS; i += NTHREADS) {
            a += g_pts[i];
            b += g_prs[i];
        }
        #pragma unroll
        for (int o = 16; o > 0; o >>= 1) {
            a += __shfl_xor_sync(0xffffffffu, a, o);
            b += __shfl_xor_sync(0xffffffffu, b, o);
        }
        __syncthreads();                 // sts/srs reuse
        if (lane == 0) { sts[warp] = a; srs[warp] = b; }
        __syncthreads();
        if (threadIdx.x == 0) {
            float A = 0.0f, B = 0.0f;
            #pragma unroll
            for (int w = 0; w < NTHREADS / 32; w++) { A += sts[w]; B += srs[w]; }
            g_ctr = 0;                   // rearm for the next graph replay
            double cnt        = 2.0 * (double)n4;           // elems / 2
            double trans_loss = (double)A / cnt;            // TRANS_WEIGHT=1
            double rot_loss   = ((double)B / cnt) * 100.0;  // ROT_WEIGHT=100
            out[0] = (float)(trans_loss + rot_loss);
            out[1] = (float)trans_loss;
            out[2] = (float)rot_loss;
        }
    }
}

extern "C" void kernel_launch(void* const* d_in, const int* in_sizes, int n_in,
                              void* d_out, int out_size) {
    const float4* pred4   = (const float4*)d_in[0];
    const float4* target4 = (const float4*)d_in[1];
    unsigned n4 = (unsigned)(in_sizes[0] / 4);

    wmse_kernel<<<NBLOCKS, NTHREADS>>>(pred4, target4, n4, (float*)d_out);
}

// round 5
// speedup vs baseline: 2.3500x; 1.1449x over previous
#include <cuda_runtime.h>

#define NBLOCKS  1152
#define NTHREADS 256
// 1152 blocks <= 1184 resident CTAs (8/SM x 148) -> single full wave.
// total = 294,912 threads, divisible by 3 -> v % 3 loop-invariant per thread.

__device__ float        g_pts[NBLOCKS];
__device__ float        g_prs[NBLOCKS];
__device__ unsigned int g_ctr = 0;   // reset by the last block each call

__device__ __forceinline__ float wrap_angle(float a) {
    const float PI  = 3.14159265358979323846f;
    const float TPI = 6.28318530717958647692f;
    a = (a >  PI) ? a - TPI : a;
    a = (a < -PI) ? a + TPI : a;
    return a;
}

__global__ void __launch_bounds__(NTHREADS)
wmse_kernel(const float4* __restrict__ p4, const float4* __restrict__ t4,
            unsigned n4, float* __restrict__ out) {
    const unsigned total = NBLOCKS * NTHREADS;     // divisible by 3
    const unsigned tid   = blockIdx.x * NTHREADS + threadIdx.x;

    // Rotation-lane pattern of float4 #v depends only on v % 3 == tid % 3:
    //   m=0 -> channels {0,1,2,3} -> rot lanes {3}
    //   m=1 -> channels {4,5,0,1} -> rot lanes {0,1}
    //   m=2 -> channels {2,3,4,5} -> rot lanes {1,2,3}
    const unsigned m = tid % 3u;
    float4 rw;                                      // 1.0 where rotation lane
    rw.x = (m == 1u) ? 1.0f : 0.0f;
    rw.y = (m != 0u) ? 1.0f : 0.0f;
    rw.z = (m == 2u) ? 1.0f : 0.0f;
    rw.w = (m != 1u) ? 1.0f : 0.0f;
    float4 tw;                                      // complement
    tw.x = 1.0f - rw.x;  tw.y = 1.0f - rw.y;
    tw.z = 1.0f - rw.z;  tw.w = 1.0f - rw.w;

    float ts = 0.0f, rs = 0.0f;

    // Simple grid-stride loop, one float4 pair per iteration.
    for (unsigned v = tid; v < n4; v += total) {
        float4 p = p4[v];
        float4 t = t4[v];

        float dx = p.x - t.x, dy = p.y - t.y, dz = p.z - t.z, dwv = p.w - t.w;
        float ex = wrap_angle(p.x) - wrap_angle(t.x);
        float ey = wrap_angle(p.y) - wrap_angle(t.y);
        float ez = wrap_angle(p.z) - wrap_angle(t.z);
        float ew = wrap_angle(p.w) - wrap_angle(t.w);

        ts = fmaf(dx * dx, tw.x, ts);
        ts = fmaf(dy * dy, tw.y, ts);
        ts = fmaf(dz * dz, tw.z, ts);
        ts = fmaf(dwv * dwv, tw.w, ts);
        rs = fmaf(ex * ex, rw.x, rs);
        rs = fmaf(ey * ey, rw.y, rs);
        rs = fmaf(ez * ez, rw.z, rs);
        rs = fmaf(ew * ew, rw.w, rs);
    }

    // Block reduction
    #pragma unroll
    for (int o = 16; o > 0; o >>= 1) {
        ts += __shfl_xor_sync(0xffffffffu, ts, o);
        rs += __shfl_xor_sync(0xffffffffu, rs, o);
    }
    __shared__ float sts[NTHREADS / 32];
    __shared__ float srs[NTHREADS / 32];
    int lane = threadIdx.x & 31;
    int warp = threadIdx.x >> 5;
    if (lane == 0) { sts[warp] = ts; srs[warp] = rs; }
    __syncthreads();

    __shared__ bool isLast;
    if (threadIdx.x == 0) {
        float bts = 0.0f, brs = 0.0f;
        #pragma unroll
        for (int w = 0; w < NTHREADS / 32; w++) { bts += sts[w]; brs += srs[w]; }
        g_pts[blockIdx.x] = bts;
        g_prs[blockIdx.x] = brs;
        __threadfence();
        unsigned prev = atomicAdd(&g_ctr, 1u);
        isLast = (prev == (unsigned)gridDim.x - 1u);
    }
    __syncthreads();

    if (isLast) {
        __threadfence();
        float a = 0.0f, b = 0.0f;
        for (unsigned i = threadIdx.x; i < NBLOCKS; i += NTHREADS) {
            a += g_pts[i];
            b += g_prs[i];
        }
        #pragma unroll
        for (int o = 16; o > 0; o >>= 1) {
            a += __shfl_xor_sync(0xffffffffu, a, o);
            b += __shfl_xor_sync(0xffffffffu, b, o);
        }
        __syncthreads();                 // sts/srs reuse
        if (lane == 0) { sts[warp] = a; srs[warp] = b; }
        __syncthreads();
        if (threadIdx.x == 0) {
            float A = 0.0f, B = 0.0f;
            #pragma unroll
            for (int w = 0; w < NTHREADS / 32; w++) { A += sts[w]; B += srs[w]; }
            g_ctr = 0;                   // rearm for the next graph replay
            double cnt        = 2.0 * (double)n4;           // elems / 2
            double trans_loss = (double)A / cnt;            // TRANS_WEIGHT=1
            double rot_loss   = ((double)B / cnt) * 100.0;  // ROT_WEIGHT=100
            out[0] = (float)(trans_loss + rot_loss);
            out[1] = (float)trans_loss;
            out[2] = (float)rot_loss;
        }
    }
}

extern "C" void kernel_launch(void* const* d_in, const int* in_sizes, int n_in,
                              void* d_out, int out_size) {
    const float4* pred4   = (const float4*)d_in[0];
    const float4* target4 = (const float4*)d_in[1];
    unsigned n4 = (unsigned)(in_sizes[0] / 4);

    wmse_kernel<<<NBLOCKS, NTHREADS>>>(pred4, target4, n4, (float*)d_out);
}